// round 1
// baseline (speedup 1.0000x reference)
#include <cuda_runtime.h>
#include <math.h>

// Problem constants (fixed shapes from reference)
#define HEADS_N 4
#define BSZ 2
#define NTOT 8192        // THW
#define MTOT 1024        // HW
#define CKTOT 64
#define CVTOT 512
#define CVH 128
#define M_T 64           // m-tile per block
#define NSPLIT 4
#define NPS (NTOT / NSPLIT)   // 2048 n per split
#define NC 32            // n chunk staged in smem
#define NTHREADS 512

// Partial accumulators: [split][b][cv][m]  (16 MB static scratch; no cudaMalloc)
__device__ __align__(16) float g_partial[NSPLIT * BSZ * CVTOT * MTOT];

struct SmemLayout {
    float Qs[HEADS_N][32][M_T];        // rows: k<16 -> -qe ; k>=16 -> 2*qk*qe
    float Kt[HEADS_N][32][NC + 1];     // rows: k<16 -> mk^3 ; k>=16 -> mk
    float Ps[HEADS_N][M_T][NC + 1];    // scores, then probabilities (layout [h][m][n])
    float mvs[CVTOT][NC + 1];          // staged mv tile
    float bias[HEADS_N][M_T];          // b_sq = sum_c qe*qk^3
    float mss[NC];                     // ms for this n chunk
};

__global__ void __launch_bounds__(NTHREADS, 1)
mem_reader_kernel(const float* __restrict__ mk, const float* __restrict__ qk,
                  const float* __restrict__ ms, const float* __restrict__ qe,
                  const float* __restrict__ mv)
{
    extern __shared__ float smem_raw[];
    SmemLayout* sm = reinterpret_cast<SmemLayout*>(smem_raw);

    const int tid   = threadIdx.x;
    const int bx    = blockIdx.x;          // 128 blocks total
    const int split = bx & 3;
    const int mtile = (bx >> 2) & 15;
    const int b     = bx >> 6;
    const int m0    = mtile * M_T;
    const int nbase = split * NPS;

    // ---- Block setup: query-side smem (Qs) and bias ----
    for (int i = tid; i < CKTOT * M_T; i += NTHREADS) {
        int row = i >> 6;            // h*16+c
        int ml  = i & 63;
        int h = row >> 4, c = row & 15;
        float qe_v = qe[(size_t)(b * CKTOT + row) * MTOT + m0 + ml];
        float qk_v = qk[(size_t)(b * CKTOT + row) * MTOT + m0 + ml];
        sm->Qs[h][c][ml]      = -qe_v;
        sm->Qs[h][16 + c][ml] = 2.0f * qk_v * qe_v;
    }
    if (tid < HEADS_N * M_T) {
        int h = tid >> 6, ml = tid & 63;
        float s = 0.0f;
        #pragma unroll
        for (int c = 0; c < 16; c++) {
            float qe_v = qe[(size_t)(b * CKTOT + h * 16 + c) * MTOT + m0 + ml];
            float qk_v = qk[(size_t)(b * CKTOT + h * 16 + c) * MTOT + m0 + ml];
            s += qe_v * qk_v * qk_v * qk_v;
        }
        sm->bias[h][ml] = s;
    }

    // ---- Phase B thread mapping: 64 cv-groups x 8 m-groups ----
    const int cvg = tid >> 3;        // 0..63 -> cv0 = cvg*8
    const int mg  = tid & 7;         // m_local = mg + 8*jm (strided: bank-friendly)
    const int hB  = cvg >> 4;        // head for readout

    // ---- Phase A thread mapping: (h, 4n, 4m) per thread ----
    const int hA  = tid >> 7;        // 0..3
    const int nq4 = ((tid >> 4) & 7) * 4;
    const int mq4 = (tid & 15) * 4;

    float acc[8][8];
    #pragma unroll
    for (int a = 0; a < 8; a++)
        #pragma unroll
        for (int j = 0; j < 8; j++) acc[a][j] = 0.0f;

    __syncthreads();

    const float inv_sqrt_ck = 0.125f;   // 1/sqrt(64)

    for (int chunk = 0; chunk < NPS / NC; chunk++) {
        const int n0 = nbase + chunk * NC;

        // ---- Stage key-side tile: mk and mk^3 (coalesced along n) ----
        for (int i = tid; i < CKTOT * NC; i += NTHREADS) {
            int row = i >> 5;        // h*16+c
            int nn  = i & 31;
            float v = mk[(size_t)(b * CKTOT + row) * NTOT + n0 + nn];
            int h = row >> 4, c = row & 15;
            sm->Kt[h][c][nn]      = v * v * v;
            sm->Kt[h][16 + c][nn] = v;
        }
        // ---- Stage mv tile (coalesced along n) ----
        for (int i = tid; i < CVTOT * NC; i += NTHREADS) {
            int row = i >> 5, nn = i & 31;
            sm->mvs[row][nn] = mv[(size_t)(b * CVTOT + row) * NTOT + n0 + nn];
        }
        if (tid < NC) sm->mss[tid] = ms[(size_t)b * NTOT + n0 + tid];
        __syncthreads();

        // ---- Phase A: raw scores, 4n x 4m register tile per thread ----
        {
            float a4[4][4];
            #pragma unroll
            for (int i = 0; i < 4; i++)
                #pragma unroll
                for (int j = 0; j < 4; j++) a4[i][j] = 0.0f;

            #pragma unroll 8
            for (int k = 0; k < 32; k++) {
                float kv[4], qv4[4];
                #pragma unroll
                for (int i = 0; i < 4; i++) kv[i]  = sm->Kt[hA][k][nq4 + i];
                #pragma unroll
                for (int j = 0; j < 4; j++) qv4[j] = sm->Qs[hA][k][mq4 + j];
                #pragma unroll
                for (int i = 0; i < 4; i++)
                    #pragma unroll
                    for (int j = 0; j < 4; j++)
                        a4[i][j] = fmaf(kv[i], qv4[j], a4[i][j]);
            }
            #pragma unroll
            for (int j = 0; j < 4; j++) {
                float bj = sm->bias[hA][mq4 + j];
                #pragma unroll
                for (int i = 0; i < 4; i++) {
                    float s = (a4[i][j] - bj) * sm->mss[nq4 + i] * inv_sqrt_ck;
                    sm->Ps[hA][mq4 + j][nq4 + i] = s;
                }
            }
        }
        __syncthreads();

        // ---- Softmax over the 4 heads (per (n,m)) ----
        for (int idx = tid; idx < NC * M_T; idx += NTHREADS) {
            int nn = idx & 31, mm = idx >> 5;
            float s0 = sm->Ps[0][mm][nn];
            float s1 = sm->Ps[1][mm][nn];
            float s2 = sm->Ps[2][mm][nn];
            float s3 = sm->Ps[3][mm][nn];
            float mx = fmaxf(fmaxf(s0, s1), fmaxf(s2, s3));
            float e0 = __expf(s0 - mx);
            float e1 = __expf(s1 - mx);
            float e2 = __expf(s2 - mx);
            float e3 = __expf(s3 - mx);
            float inv = __fdividef(1.0f, e0 + e1 + e2 + e3);
            sm->Ps[0][mm][nn] = e0 * inv;
            sm->Ps[1][mm][nn] = e1 * inv;
            sm->Ps[2][mm][nn] = e2 * inv;
            sm->Ps[3][mm][nn] = e3 * inv;
        }
        __syncthreads();

        // ---- Phase B: readout GEMM, 8cv x 8m per thread ----
        #pragma unroll 2
        for (int nn = 0; nn < NC; nn++) {
            float pv[8];
            #pragma unroll
            for (int jm = 0; jm < 8; jm++)
                pv[jm] = sm->Ps[hB][mg + 8 * jm][nn];
            #pragma unroll
            for (int jc = 0; jc < 8; jc++) {
                float mvv = sm->mvs[cvg * 8 + jc][nn];
                #pragma unroll
                for (int jm = 0; jm < 8; jm++)
                    acc[jc][jm] = fmaf(mvv, pv[jm], acc[jc][jm]);
            }
        }
        __syncthreads();
    }

    // ---- Write partial sums ----
    float* pp = g_partial + ((size_t)(split * BSZ + b) * CVTOT) * MTOT;
    #pragma unroll
    for (int jc = 0; jc < 8; jc++) {
        int cv = cvg * 8 + jc;
        #pragma unroll
        for (int jm = 0; jm < 8; jm++)
            pp[(size_t)cv * MTOT + m0 + mg + 8 * jm] = acc[jc][jm];
    }
}

// Reduce the 4 n-split partials into out[:, 0:512, :, :] and copy qv into
// out[:, 512:1024, :, :]. Vectorized float4.
__global__ void assemble_kernel(const float* __restrict__ qv, float* __restrict__ out)
{
    const int total4 = BSZ * 2 * CVTOT * MTOT / 4;  // 524288
    int idx = blockIdx.x * blockDim.x + threadIdx.x;
    if (idx >= total4) return;
    int gf  = idx * 4;
    int b   = gf >> 20;                  // 1024*1024 floats per batch
    int rem = gf & ((1 << 20) - 1);
    int ch  = rem >> 10;
    int m   = rem & 1023;

    float4 r;
    if (ch < CVTOT) {
        const size_t stride = (size_t)BSZ * CVTOT * MTOT;
        size_t off = ((size_t)b * CVTOT + ch) * MTOT + m;
        float4 a0 = *reinterpret_cast<const float4*>(g_partial + 0 * stride + off);
        float4 a1 = *reinterpret_cast<const float4*>(g_partial + 1 * stride + off);
        float4 a2 = *reinterpret_cast<const float4*>(g_partial + 2 * stride + off);
        float4 a3 = *reinterpret_cast<const float4*>(g_partial + 3 * stride + off);
        r.x = a0.x + a1.x + a2.x + a3.x;
        r.y = a0.y + a1.y + a2.y + a3.y;
        r.z = a0.z + a1.z + a2.z + a3.z;
        r.w = a0.w + a1.w + a2.w + a3.w;
    } else {
        r = *reinterpret_cast<const float4*>(
                qv + ((size_t)b * CVTOT + (ch - CVTOT)) * MTOT + m);
    }
    *reinterpret_cast<float4*>(out + (size_t)gf) = r;
}

extern "C" void kernel_launch(void* const* d_in, const int* in_sizes, int n_in,
                              void* d_out, int out_size)
{
    const float* mk = (const float*)d_in[0];
    const float* qk = (const float*)d_in[1];
    const float* ms = (const float*)d_in[2];
    const float* qe = (const float*)d_in[3];
    const float* mv = (const float*)d_in[4];
    const float* qv = (const float*)d_in[5];
    float* out = (float*)d_out;

    cudaFuncSetAttribute(mem_reader_kernel,
                         cudaFuncAttributeMaxDynamicSharedMemorySize,
                         (int)sizeof(SmemLayout));

    mem_reader_kernel<<<BSZ * 16 * NSPLIT, NTHREADS, sizeof(SmemLayout)>>>(
        mk, qk, ms, qe, mv);

    const int total4 = BSZ * 2 * CVTOT * MTOT / 4;
    assemble_kernel<<<(total4 + 255) / 256, 256>>>(qv, out);
}